// round 6
// baseline (speedup 1.0000x reference)
#include <cuda_runtime.h>
#include <math.h>
#include <stdint.h>

// ---------------------------------------------------------------------------
// BidirectionalAttentionalPromptEncoder — batch-invariant (B=1) formulation.
// R6: LSTM dot reads h directly from L2 (__ldcg) — no smem staging, one fewer
// syncthreads per step. GEMMs identical to R5 (tf32 mma, split-K).
// ---------------------------------------------------------------------------

// ----------------------------- scratch --------------------------------------
#define OFF_X    0          // [4][64][1024]
#define OFF_XZ   262144     // [8][64][2048]
#define OFF_Y0   1310720    // [4][64][1024]
#define OFF_Y1   1572864    // [4][64][1024]
#define OFF_HB   1835008    // [2][8][512]
#define OFF_G0   1847296    // [2][64][2048]
#define OFF_GH   2109440    // [2][64][1024]
#define OFF_GH2  2240512    // [2][64][1024]
#define OFF_GG   2371584    // [2][64][2048]
#define OFF_BI   2633728    // [2][64][1024]
#define OFF_Q    2764800
#define OFF_K    2895872
#define OFF_V    3026944
#define OFF_AO   3158016
#define OFF_PA   3289088
#define OFF_LNO  3420160
#define OFF_T1   3551232    // [2][64][2048]
#define OFF_T2   3813376    // [2][64][2048]
#define OFF_T3   4075520    // [2][64][1024]
#define OFF_RES  4206592    // [2][64][1024]
#define OFF_PART 4337664    // split-K partials
#define SCRATCH_TOTAL 6434816

__device__ float g_scratch[SCRATCH_TOTAL];

// per-group barrier counters, one cache line apart; monotonic within a launch,
// zeroed by embed_kernel at the start of every launch/replay.
__device__ unsigned g_grp_cnt[4 * 32];

__device__ __forceinline__ float sigf(float x) { return 1.0f / (1.0f + expf(-x)); }

__device__ __forceinline__ void bar_red_release(unsigned* cnt) {
    asm volatile("red.release.gpu.global.add.u32 [%0], %1;"
                 :: "l"(cnt), "r"(1u) : "memory");
}
__device__ __forceinline__ unsigned ld_acquire(unsigned* p) {
    unsigned v;
    asm volatile("ld.acquire.gpu.global.u32 %0, [%1];"
                 : "=r"(v) : "l"(p) : "memory");
    return v;
}
__device__ __forceinline__ uint32_t f2tf32(float x) {
    uint32_t r; asm("cvt.rna.tf32.f32 %0, %1;" : "=r"(r) : "f"(x)); return r;
}

// ----------------------------- embedding ------------------------------------
__global__ void embed_kernel(const float* __restrict__ pre,
                             const float* __restrict__ suf) {
    if (blockIdx.x == 0 && threadIdx.x < 128) g_grp_cnt[threadIdx.x] = 0;
    int idx = blockIdx.x * 256 + threadIdx.x;   // < 4*64*1024
    int b = idx >> 16;
    int t = (idx >> 10) & 63;
    int c = idx & 1023;
    int st = (b >= 2) ? (63 - t) : t;
    const float* e = (b & 1) ? suf : pre;
    int i2 = c & ~1;
    double div = exp(-log(10000.0) * (double)i2 / 1024.0);
    double ang = (double)st * div;
    float pe = (c & 1) ? (float)cos(ang) : (float)sin(ang);
    g_scratch[OFF_X + idx] = e[st * 1024 + c] + pe;
}

// --------------------------- tf32 tensor GEMM -------------------------------
struct GemmSK {
    const float* A[8];
    const float* W[8];
};
struct RedB {
    const float* b1[8];
    const float* b2[8];
    float*       O[8];
};

__global__ void __launch_bounds__(256, 2) gemm_tc(GemmSK p, float* part,
                                                  int N, int K, int chunkK) {
    __shared__ uint32_t As[64][20];
    __shared__ uint32_t Ws[128][20];
    int bz = blockIdx.y, kc = blockIdx.z;
    const float* A = p.A[bz];
    const float* W = p.W[bz];
    int n0 = blockIdx.x * 128;
    int tid = threadIdx.x;
    int warp = tid >> 5, lane = tid & 31;
    int mt = warp & 3, nh = warp >> 2;
    int gid = lane >> 2, tig = lane & 3;

    float c[8][4];
#pragma unroll
    for (int i = 0; i < 8; i++)
#pragma unroll
        for (int j = 0; j < 4; j++) c[i][j] = 0.0f;

    int kbeg = kc * chunkK, kend = kbeg + chunkK;
    for (int k0 = kbeg; k0 < kend; k0 += 16) {
        {   // A tile 64x16 -> tf32
            int m = tid >> 2, kq = (tid & 3) * 4;
            float4 v = *(const float4*)(A + (size_t)m * K + k0 + kq);
            uint4 u = make_uint4(f2tf32(v.x), f2tf32(v.y), f2tf32(v.z), f2tf32(v.w));
            *(uint4*)&As[m][kq] = u;
        }
#pragma unroll
        for (int l = 0; l < 2; l++) {   // W tile 128x16 -> tf32
            int s = tid * 2 + l;
            int n = s >> 2, kq = (s & 3) * 4;
            float4 v = *(const float4*)(W + (size_t)(n0 + n) * K + k0 + kq);
            uint4 u = make_uint4(f2tf32(v.x), f2tf32(v.y), f2tf32(v.z), f2tf32(v.w));
            *(uint4*)&Ws[n][kq] = u;
        }
        __syncthreads();
#pragma unroll
        for (int ks = 0; ks < 2; ks++) {
            int kb = ks * 8;
            uint32_t a0 = As[mt * 16 + gid][kb + tig];
            uint32_t a1 = As[mt * 16 + gid + 8][kb + tig];
            uint32_t a2 = As[mt * 16 + gid][kb + tig + 4];
            uint32_t a3 = As[mt * 16 + gid + 8][kb + tig + 4];
#pragma unroll
            for (int nf = 0; nf < 8; nf++) {
                uint32_t b0 = Ws[nh * 64 + nf * 8 + gid][kb + tig];
                uint32_t b1 = Ws[nh * 64 + nf * 8 + gid][kb + tig + 4];
                asm volatile(
                    "mma.sync.aligned.m16n8k8.row.col.f32.tf32.tf32.f32 "
                    "{%0,%1,%2,%3}, {%4,%5,%6,%7}, {%8,%9}, {%0,%1,%2,%3};"
                    : "+f"(c[nf][0]), "+f"(c[nf][1]), "+f"(c[nf][2]), "+f"(c[nf][3])
                    : "r"(a0), "r"(a1), "r"(a2), "r"(a3), "r"(b0), "r"(b1));
            }
        }
        __syncthreads();
    }

    float* outp = part + (size_t)(kc * gridDim.y + bz) * 64 * N;
    int m0 = mt * 16 + gid;
    int nb = n0 + nh * 64 + tig * 2;
#pragma unroll
    for (int nf = 0; nf < 8; nf++) {
        int n = nb + nf * 8;
        *(float2*)(outp + (size_t)m0 * N + n)       = make_float2(c[nf][0], c[nf][1]);
        *(float2*)(outp + (size_t)(m0 + 8) * N + n) = make_float2(c[nf][2], c[nf][3]);
    }
}

__global__ void reduce_bias(const float* __restrict__ part, RedB rb,
                            int N, int KS, int nBatch) {
    int bz = blockIdx.y;
    int idx = blockIdx.x * 256 + threadIdx.x;
    float s = 0.f;
    size_t per = (size_t)64 * N;
    for (int ks = 0; ks < KS; ks++)
        s += part[(size_t)(ks * nBatch + bz) * per + idx];
    int n = idx & (N - 1);
    if (rb.b1[bz]) s += rb.b1[bz][n];
    if (rb.b2[bz]) s += rb.b2[bz][n];
    rb.O[bz][idx] = s;
}

// ------------------------ persistent LSTM layer ------------------------------
// 128 CTAs (1/SM). CTA = (group g = lstm*2+dir, 16-unit chunk). Weights + the
// CTA's XZ slice in SMEM for all 64 timesteps. Cross-CTA h exchange via
// release/acquire counter barrier per group (32 CTAs); dot reads h straight
// from L2 (__ldcg, warp-broadcast) — no smem staging.
__global__ void __launch_bounds__(256, 1) lstm_persistent(
    const float* __restrict__ Whh, int layer) {
    extern __shared__ float smem[];
    float* sw  = smem;                 // [64][516] weight rows
    float* xzs = smem + 64 * 516;      // [2][64][64]

    float* XZ = g_scratch + OFF_XZ;
    float* Hb = g_scratch + OFF_HB;
    float* Y  = g_scratch + (layer == 0 ? OFF_Y0 : OFF_Y1);

    int blk = blockIdx.x;
    int g = blk >> 5;                  // lstm*2+dir
    int chunk = blk & 31;
    int lstm = g >> 1, dir = g & 1;
    int scanA = lstm * 4 + dir;
    int scanB = lstm * 4 + 2 + dir;
    int u0 = chunk * 16;
    const float* Wg = Whh + (size_t)((lstm * 2 + layer) * 2 + dir) * (2048 * 512);
    int tid = threadIdx.x;
    unsigned* cnt = &g_grp_cnt[g * 32];
    unsigned base = (unsigned)layer * 2048u;

    // weights: row r = gate*16+u  ->  global row gate*512+u0+u
    for (int i4 = tid; i4 < 8192; i4 += 256) {
        int r = i4 >> 7, c4 = i4 & 127;
        int grow = (r >> 4) * 512 + u0 + (r & 15);
        float4 v = *(const float4*)(Wg + (size_t)grow * 512 + c4 * 4);
        *(float4*)(sw + r * 516 + c4 * 4) = v;
    }
    // xz slice: [sB][t][r]
    for (int i = tid; i < 8192; i += 256) {
        int sB = i >> 12, t = (i >> 6) & 63, r = i & 63;
        int scan = sB ? scanB : scanA;
        int row = (r >> 4) * 512 + u0 + (r & 15);
        xzs[i] = XZ[(size_t)(scan * 64 + t) * 2048 + row];
    }
    // init h buffer 0 for our slice
    if (tid < 32) {
        int sB = tid >> 4, uu = tid & 15;
        int scan = sB ? scanB : scanA;
        Hb[scan * 512 + u0 + uu] = 0.f;
    }
    __syncthreads();
    if (tid == 0) {
        bar_red_release(cnt);
        unsigned tgt = base + 32u;
        while (ld_acquire(cnt) < tgt) {}
    }
    __syncthreads();

    __shared__ float part[2][4][64];

    float cstate = 0.f;
    int mySB = tid >> 4, myU = tid & 15;
    int myScan = mySB ? scanB : scanA;
    int r = tid & 63, pp = tid >> 6;
    const float4* wr = (const float4*)(sw + r * 516 + pp * 128);

    for (int j = 0; j < 64; j++) {
        int t = dir ? (63 - j) : j;
        const float* Hp = Hb + (j & 1) * 4096;
        {
            const float4* a4 = (const float4*)(Hp + scanA * 512 + pp * 128);
            const float4* b4 = (const float4*)(Hp + scanB * 512 + pp * 128);
            float accA0 = 0.f, accA1 = 0.f, accB0 = 0.f, accB1 = 0.f;
#pragma unroll
            for (int i = 0; i < 32; i += 2) {
                float4 w0 = wr[i],   a0 = __ldcg(a4 + i),     b0 = __ldcg(b4 + i);
                float4 w1 = wr[i+1], a1 = __ldcg(a4 + i + 1), b1 = __ldcg(b4 + i + 1);
                accA0 += w0.x * a0.x + w0.y * a0.y + w0.z * a0.z + w0.w * a0.w;
                accB0 += w0.x * b0.x + w0.y * b0.y + w0.z * b0.z + w0.w * b0.w;
                accA1 += w1.x * a1.x + w1.y * a1.y + w1.z * a1.z + w1.w * a1.w;
                accB1 += w1.x * b1.x + w1.y * b1.y + w1.z * b1.z + w1.w * b1.w;
            }
            part[0][pp][r] = accA0 + accA1;
            part[1][pp][r] = accB0 + accB1;
        }
        __syncthreads();
        float* Hnext = Hb + ((j + 1) & 1) * 4096;
        if (tid < 32) {
            float z[4];
#pragma unroll
            for (int gg = 0; gg < 4; gg++) {
                int rr = gg * 16 + myU;
                z[gg] = xzs[mySB * 4096 + t * 64 + rr]
                      + part[mySB][0][rr] + part[mySB][1][rr]
                      + part[mySB][2][rr] + part[mySB][3][rr];
            }
            float c = sigf(z[1]) * cstate + sigf(z[0]) * tanhf(z[2]);
            float h = sigf(z[3]) * tanhf(c);
            cstate = c;
            Hnext[myScan * 512 + u0 + myU] = h;
            int seq = lstm * 2 + mySB;
            Y[(size_t)(seq * 64 + t) * 1024 + dir * 512 + u0 + myU] = h;
        }
        if (j == 63) break;
        if (tid < 32) __syncwarp(0xffffffffu);     // order warp0's STGs before release
        if (tid == 0) {
            bar_red_release(cnt);
            unsigned tgt = base + (unsigned)(j + 2) * 32u;
            while (ld_acquire(cnt) < tgt) {}
        }
        __syncthreads();
    }
}

// ------------------------- gate input / combine -----------------------------
__global__ void gatein_kernel() {
    int idx = blockIdx.x * 256 + threadIdx.x;   // < 2*64*2048
    int i = idx >> 17;
    int rem = idx & 131071;
    int t = rem >> 11;
    int c = rem & 2047;
    const float* Y1 = g_scratch + OFF_Y1;
    float v;
    if (c < 1024) v = Y1[(size_t)(i * 64 + t) * 1024 + c];
    else          v = Y1[(size_t)((i + 2) * 64 + (63 - t)) * 1024 + (c - 1024)];
    g_scratch[OFF_G0 + idx] = v;
}

__global__ void combine_kernel() {
    int idx = blockIdx.x * 256 + threadIdx.x;   // < 2*64*1024
    int i = idx >> 16;
    int rem = idx & 65535;
    int t = rem >> 10;
    int c = rem & 1023;
    const float* GG = g_scratch + OFF_GG;
    const float* Y1 = g_scratch + OFF_Y1;
    float fg = sigf(GG[(size_t)i * 131072 + t * 2048 + c]);
    float bg = sigf(GG[(size_t)i * 131072 + t * 2048 + 1024 + c]);
    float f = Y1[(size_t)(i * 64 + t) * 1024 + c];
    float b = Y1[(size_t)((i + 2) * 64 + (63 - t)) * 1024 + c];
    g_scratch[OFF_BI + idx] = fg * f + bg * b;
}

// -------------------------- layernorm (+gelu, +add) -------------------------
__global__ void ln_kernel(const float* __restrict__ in, const float* __restrict__ add,
                          const float* __restrict__ gamma, const float* __restrict__ beta,
                          float* __restrict__ out, int N, int dogelu, int perhalf) {
    int row = blockIdx.x;
    const float* x = in + (size_t)row * N;
    const float* ad = add ? add + (size_t)row * N : nullptr;
    int goff = perhalf ? (row >> 6) * N : 0;
    __shared__ float red[256];
    int tid = threadIdx.x;
    float s = 0.f;
    for (int i = tid; i < N; i += 256) { float v = x[i] + (ad ? ad[i] : 0.f); s += v; }
    red[tid] = s; __syncthreads();
    for (int o = 128; o > 0; o >>= 1) { if (tid < o) red[tid] += red[tid + o]; __syncthreads(); }
    float mean = red[0] / N;
    __syncthreads();
    float v2 = 0.f;
    for (int i = tid; i < N; i += 256) {
        float v = x[i] + (ad ? ad[i] : 0.f) - mean; v2 += v * v;
    }
    red[tid] = v2; __syncthreads();
    for (int o = 128; o > 0; o >>= 1) { if (tid < o) red[tid] += red[tid + o]; __syncthreads(); }
    float inv = rsqrtf(red[0] / N + 1e-5f);
    for (int i = tid; i < N; i += 256) {
        float v = (x[i] + (ad ? ad[i] : 0.f) - mean) * inv * gamma[goff + i] + beta[goff + i];
        if (dogelu) v = 0.5f * v * (1.0f + erff(v * 0.70710678118654752f));
        out[(size_t)row * N + i] = v;
    }
}

// ----------------------------- attention core -------------------------------
__global__ void __launch_bounds__(256) attn_core_kernel() {
    const int h = blockIdx.x;
    const int a = blockIdx.y;
    const float* Q = g_scratch + OFF_Q + (size_t)a * 64 * 1024;
    const float* K = g_scratch + OFF_K + (size_t)a * 64 * 1024;
    const float* V = g_scratch + OFF_V + (size_t)a * 64 * 1024;
    float* AO = g_scratch + OFF_AO + (size_t)a * 64 * 1024;
    __shared__ float KV[64][128];
    __shared__ float Ssm[64][64];
    int tid = threadIdx.x;

    for (int i = tid; i < 64 * 128; i += 256) {
        int m = i >> 7, d = i & 127;
        KV[m][d] = K[m * 1024 + h * 128 + d];
    }
    __syncthreads();
    {
        int n = tid >> 2, p = tid & 3;
        float acc[16];
#pragma unroll
        for (int i = 0; i < 16; i++) acc[i] = 0.f;
        const float* q = Q + n * 1024 + h * 128;
        for (int d = 0; d < 128; d++) {
            float qv = q[d];
#pragma unroll
            for (int i = 0; i < 16; i++) acc[i] += qv * KV[p * 16 + i][d];
        }
        const float scale = 0.08838834764831845f;
#pragma unroll
        for (int i = 0; i < 16; i++) Ssm[n][p * 16 + i] = acc[i] * scale;
    }
    __syncthreads();
    for (int i = tid; i < 64 * 128; i += 256) {
        int m = i >> 7, d = i & 127;
        KV[m][d] = V[m * 1024 + h * 128 + d];
    }
    if (tid < 64) {
        float mx = -1e30f;
        for (int m = 0; m < 64; m++) mx = fmaxf(mx, Ssm[tid][m]);
        float sum = 0.f;
        for (int m = 0; m < 64; m++) { float e = expf(Ssm[tid][m] - mx); Ssm[tid][m] = e; sum += e; }
        float invs = 1.f / sum;
        for (int m = 0; m < 64; m++) Ssm[tid][m] *= invs;
    }
    __syncthreads();
    {
        int n = tid >> 2, p = tid & 3;
        float acc[32];
#pragma unroll
        for (int i = 0; i < 32; i++) acc[i] = 0.f;
        for (int m = 0; m < 64; m++) {
            float w = Ssm[n][m];
#pragma unroll
            for (int i = 0; i < 32; i++) acc[i] += w * KV[m][p * 32 + i];
        }
        for (int i = 0; i < 32; i++)
            AO[n * 1024 + h * 128 + p * 32 + i] = acc[i];
    }
}

// ------------------------------ broadcast -----------------------------------
__global__ void broadcast_kernel(float* __restrict__ out, int total, int half_elems) {
    int j = blockIdx.x * 256 + threadIdx.x;
    if (j >= total) return;
    int half = j / half_elems;
    int rem = j - half * half_elems;
    int i = rem & 65535;
    out[j] = g_scratch[OFF_RES + half * 65536 + i];
}

// ------------------------------- launcher -----------------------------------
extern "C" void kernel_launch(void* const* d_in, const int* in_sizes, int n_in,
                              void* d_out, int out_size) {
    const float* prefix  = (const float*)d_in[0];
    const float* suffix  = (const float*)d_in[1];
    const float* Wih     = (const float*)d_in[2];
    const float* Whh     = (const float*)d_in[3];
    const float* bih     = (const float*)d_in[4];
    const float* bhh     = (const float*)d_in[5];
    const float* attn_w  = (const float*)d_in[6];
    const float* attn_b  = (const float*)d_in[7];
    const float* gate_w1 = (const float*)d_in[8];
    const float* gate_b1 = (const float*)d_in[9];
    const float* gate_lg = (const float*)d_in[10];
    const float* gate_lb = (const float*)d_in[11];
    const float* gate_w2 = (const float*)d_in[12];
    const float* gate_b2 = (const float*)d_in[13];
    const float* out_w1  = (const float*)d_in[14];
    const float* out_b1  = (const float*)d_in[15];
    const float* out_g1  = (const float*)d_in[16];
    const float* out_be1 = (const float*)d_in[17];
    const float* out_w2  = (const float*)d_in[18];
    const float* out_b2  = (const float*)d_in[19];
    const float* out_g2  = (const float*)d_in[20];
    const float* out_be2 = (const float*)d_in[21];
    const float* ln_g    = (const float*)d_in[22];
    const float* ln_b    = (const float*)d_in[23];
    float* out = (float*)d_out;

    float* S = nullptr;
    cudaGetSymbolAddress((void**)&S, g_scratch);
    float* X    = S + OFF_X;
    float* XZ   = S + OFF_XZ;
    float* Y0   = S + OFF_Y0;
    float* G0   = S + OFF_G0;
    float* GH   = S + OFF_GH;
    float* GH2  = S + OFF_GH2;
    float* GG   = S + OFF_GG;
    float* BI   = S + OFF_BI;
    float* Qp   = S + OFF_Q;
    float* Kp   = S + OFF_K;
    float* Vp   = S + OFF_V;
    float* AO   = S + OFF_AO;
    float* PA   = S + OFF_PA;
    float* LNO  = S + OFF_LNO;
    float* T1   = S + OFF_T1;
    float* T2   = S + OFF_T2;
    float* T3   = S + OFF_T3;
    float* PART = S + OFF_PART;

    const int LSTM_SMEM = (64 * 516 + 8192) * 4;
    static int smem_set = 0;
    if (!smem_set) {
        cudaFuncSetAttribute(lstm_persistent,
                             cudaFuncAttributeMaxDynamicSharedMemorySize, LSTM_SMEM);
        smem_set = 1;
    }

    // 1) embed + PE (zeroes barrier counters)
    embed_kernel<<<1024, 256>>>(prefix, suffix);

    // 2) bilstm
    for (int layer = 0; layer < 2; layer++) {
        const float* src = (layer == 0) ? X : Y0;
        GemmSK gs; RedB rb;
        for (int s = 0; s < 8; s++) {
            int seq = s >> 1, dir = s & 1, lstm = seq >> 1;
            int wi = (lstm * 2 + layer) * 2 + dir;
            gs.A[s]  = src + (size_t)seq * 64 * 1024;
            gs.W[s]  = Wih + (size_t)wi * 2048 * 1024;
            rb.b1[s] = bih + (size_t)wi * 2048;
            rb.b2[s] = bhh + (size_t)wi * 2048;
            rb.O[s]  = XZ + (size_t)s * 64 * 2048;
        }
        gemm_tc<<<dim3(16, 8, 2), 256>>>(gs, PART, 2048, 1024, 512);
        reduce_bias<<<dim3(512, 8), 256>>>(PART, rb, 2048, 2, 8);
        lstm_persistent<<<128, 256, LSTM_SMEM>>>(Whh, layer);
    }

    // 3) gates
    gatein_kernel<<<1024, 256>>>();
    {
        GemmSK gs; RedB rb;
        for (int i = 0; i < 2; i++) {
            gs.A[i]  = G0 + (size_t)i * 64 * 2048;
            gs.W[i]  = gate_w1 + (size_t)i * 1024 * 2048;
            rb.b1[i] = gate_b1 + (size_t)i * 1024;
            rb.b2[i] = nullptr;
            rb.O[i]  = GH + (size_t)i * 64 * 1024;
        }
        gemm_tc<<<dim3(8, 2, 16), 256>>>(gs, PART, 1024, 2048, 128);
        reduce_bias<<<dim3(256, 2), 256>>>(PART, rb, 1024, 16, 2);
    }
    ln_kernel<<<128, 256>>>(GH, nullptr, gate_lg, gate_lb, GH2, 1024, 1, 1);
    {
        GemmSK gs; RedB rb;
        for (int i = 0; i < 2; i++) {
            gs.A[i]  = GH2 + (size_t)i * 64 * 1024;
            gs.W[i]  = gate_w2 + (size_t)i * 2048 * 1024;
            rb.b1[i] = gate_b2 + (size_t)i * 2048;
            rb.b2[i] = nullptr;
            rb.O[i]  = GG + (size_t)i * 64 * 2048;
        }
        gemm_tc<<<dim3(16, 2, 8), 256>>>(gs, PART, 2048, 1024, 128);
        reduce_bias<<<dim3(512, 2), 256>>>(PART, rb, 2048, 8, 2);
    }
    combine_kernel<<<512, 256>>>();

    // 4) cross attention
    {
        GemmSK gs; RedB rb;
        for (int a = 0; a < 2; a++)
            for (int k3 = 0; k3 < 3; k3++) {
                int e = a * 3 + k3;
                int srcIdx = (k3 == 0) ? a : (1 - a);
                gs.A[e]  = BI + (size_t)srcIdx * 64 * 1024;
                gs.W[e]  = attn_w + (size_t)(a * 4 + k3) * 1024 * 1024;
                rb.b1[e] = attn_b + (size_t)(a * 4 + k3) * 1024;
                rb.b2[e] = nullptr;
                float* dst = (k3 == 0) ? Qp : (k3 == 1) ? Kp : Vp;
                rb.O[e]  = dst + (size_t)a * 64 * 1024;
            }
        gemm_tc<<<dim3(8, 6, 4), 256>>>(gs, PART, 1024, 1024, 256);
        reduce_bias<<<dim3(256, 6), 256>>>(PART, rb, 1024, 4, 6);
    }
    attn_core_kernel<<<dim3(8, 2), 256>>>();
    {
        GemmSK gs; RedB rb;
        for (int a = 0; a < 2; a++) {
            gs.A[a]  = AO + (size_t)a * 64 * 1024;
            gs.W[a]  = attn_w + (size_t)(a * 4 + 3) * 1024 * 1024;
            rb.b1[a] = attn_b + (size_t)(a * 4 + 3) * 1024;
            rb.b2[a] = nullptr;
            rb.O[a]  = PA + (size_t)a * 64 * 1024;
        }
        gemm_tc<<<dim3(8, 2, 16), 256>>>(gs, PART, 1024, 1024, 64);
        reduce_bias<<<dim3(256, 2), 256>>>(PART, rb, 1024, 16, 2);
    }
    ln_kernel<<<128, 256>>>(BI, PA, ln_g, ln_b, LNO, 1024, 0, 0);

    // 5) output transforms
    {
        GemmSK gs; RedB rb;
        for (int i = 0; i < 2; i++) {
            gs.A[i]  = LNO + (size_t)i * 64 * 1024;
            gs.W[i]  = out_w1 + (size_t)i * 2048 * 1024;
            rb.b1[i] = out_b1 + (size_t)i * 2048;
            rb.b2[i] = nullptr;
            rb.O[i]  = T1 + (size_t)i * 64 * 2048;
        }
        gemm_tc<<<dim3(16, 2, 8), 256>>>(gs, PART, 2048, 1024, 128);
        reduce_bias<<<dim3(512, 2), 256>>>(PART, rb, 2048, 8, 2);
    }
    ln_kernel<<<128, 256>>>(T1, nullptr, out_g1, out_be1, T2, 2048, 1, 1);
    {
        GemmSK gs; RedB rb;
        for (int i = 0; i < 2; i++) {
            gs.A[i]  = T2 + (size_t)i * 64 * 2048;
            gs.W[i]  = out_w2 + (size_t)i * 1024 * 2048;
            rb.b1[i] = out_b2 + (size_t)i * 1024;
            rb.b2[i] = nullptr;
            rb.O[i]  = T3 + (size_t)i * 64 * 1024;
        }
        gemm_tc<<<dim3(8, 2, 16), 256>>>(gs, PART, 1024, 2048, 128);
        reduce_bias<<<dim3(256, 2), 256>>>(PART, rb, 1024, 16, 2);
    }
    ln_kernel<<<128, 256>>>(T3, nullptr, out_g2, out_be2, S + OFF_RES, 1024, 0, 1);

    // 6) broadcast to all batch rows
    int half_elems = out_size / 2;
    int blocks = (out_size + 255) / 256;
    broadcast_kernel<<<blocks, 256>>>(out, out_size, half_elems);
}

// round 7
// speedup vs baseline: 1.1805x; 1.1805x over previous
#include <cuda_runtime.h>
#include <math.h>
#include <stdint.h>

// ---------------------------------------------------------------------------
// BidirectionalAttentionalPromptEncoder — batch-invariant (B=1) formulation.
// R7: LSTM reverted to R5 (best known); non-LSTM fusions:
//   - gate-1 GEMM gathers concat(f, flip(b)) in the A loader (no gatein)
//   - reduce_ln: split-K reduce + bias + LN(+gelu)(+residual) in one kernel
//   - reduce_combine: split-K reduce + sigmoid gate combine in one kernel
// ---------------------------------------------------------------------------

// ----------------------------- scratch --------------------------------------
#define OFF_X    0          // [4][64][1024]
#define OFF_XZ   262144     // [8][64][2048]
#define OFF_Y0   1310720    // [4][64][1024]
#define OFF_Y1   1572864    // [4][64][1024]
#define OFF_HB   1835008    // [2][8][512]
#define OFF_GH2  2240512    // [2][64][1024]
#define OFF_BI   2633728    // [2][64][1024]
#define OFF_Q    2764800
#define OFF_K    2895872
#define OFF_V    3026944
#define OFF_AO   3158016
#define OFF_LNO  3420160
#define OFF_T2   3813376    // [2][64][2048]
#define OFF_RES  4206592    // [2][64][1024]
#define OFF_PART 4337664    // split-K partials
#define SCRATCH_TOTAL 6434816

__device__ float g_scratch[SCRATCH_TOTAL];

// per-group barrier counters, one cache line apart; monotonic within a launch,
// zeroed by embed_kernel at the start of every launch/replay.
__device__ unsigned g_grp_cnt[4 * 32];

__device__ __forceinline__ float sigf(float x) { return 1.0f / (1.0f + expf(-x)); }

__device__ __forceinline__ void bar_red_release(unsigned* cnt) {
    asm volatile("red.release.gpu.global.add.u32 [%0], %1;"
                 :: "l"(cnt), "r"(1u) : "memory");
}
__device__ __forceinline__ unsigned ld_acquire(unsigned* p) {
    unsigned v;
    asm volatile("ld.acquire.gpu.global.u32 %0, [%1];"
                 : "=r"(v) : "l"(p) : "memory");
    return v;
}
__device__ __forceinline__ uint32_t f2tf32(float x) {
    uint32_t r; asm("cvt.rna.tf32.f32 %0, %1;" : "=r"(r) : "f"(x)); return r;
}

// ----------------------------- embedding ------------------------------------
__global__ void embed_kernel(const float* __restrict__ pre,
                             const float* __restrict__ suf) {
    if (blockIdx.x == 0 && threadIdx.x < 128) g_grp_cnt[threadIdx.x] = 0;
    int idx = blockIdx.x * 256 + threadIdx.x;   // < 4*64*1024
    int b = idx >> 16;
    int t = (idx >> 10) & 63;
    int c = idx & 1023;
    int st = (b >= 2) ? (63 - t) : t;
    const float* e = (b & 1) ? suf : pre;
    int i2 = c & ~1;
    double div = exp(-log(10000.0) * (double)i2 / 1024.0);
    double ang = (double)st * div;
    float pe = (c & 1) ? (float)cos(ang) : (float)sin(ang);
    g_scratch[OFF_X + idx] = e[st * 1024 + c] + pe;
}

// --------------------------- tf32 tensor GEMM -------------------------------
// partial[kc][bz] = A[64,K] · W[N,K]^T over K-chunk kc. Block tile 64x128.
// gather mode: logical A[m,k] = (k<1024) ? A[m*1024+k] : A2[(63-m)*1024+k-1024].
struct GemmSK {
    const float* A[8];
    const float* A2[8];
    const float* W[8];
};
struct RedB {
    const float* b1[8];
    const float* b2[8];
    float*       O[8];
};

__global__ void __launch_bounds__(256, 2) gemm_tc(GemmSK p, float* part,
                                                  int N, int K, int chunkK,
                                                  int gather) {
    __shared__ uint32_t As[64][20];
    __shared__ uint32_t Ws[128][20];
    int bz = blockIdx.y, kc = blockIdx.z;
    const float* A  = p.A[bz];
    const float* A2 = p.A2[bz];
    const float* W  = p.W[bz];
    int n0 = blockIdx.x * 128;
    int tid = threadIdx.x;
    int warp = tid >> 5, lane = tid & 31;
    int mt = warp & 3, nh = warp >> 2;
    int gid = lane >> 2, tig = lane & 3;

    float c[8][4];
#pragma unroll
    for (int i = 0; i < 8; i++)
#pragma unroll
        for (int j = 0; j < 4; j++) c[i][j] = 0.0f;

    int kbeg = kc * chunkK, kend = kbeg + chunkK;
    for (int k0 = kbeg; k0 < kend; k0 += 16) {
        {   // A tile 64x16 -> tf32
            int m = tid >> 2, kq = (tid & 3) * 4;
            const float* src;
            if (gather) {
                if (k0 < 1024) src = A  + (size_t)m * 1024 + k0 + kq;
                else           src = A2 + (size_t)(63 - m) * 1024 + (k0 - 1024) + kq;
            } else {
                src = A + (size_t)m * K + k0 + kq;
            }
            float4 v = *(const float4*)src;
            uint4 u = make_uint4(f2tf32(v.x), f2tf32(v.y), f2tf32(v.z), f2tf32(v.w));
            *(uint4*)&As[m][kq] = u;
        }
#pragma unroll
        for (int l = 0; l < 2; l++) {   // W tile 128x16 -> tf32
            int s = tid * 2 + l;
            int n = s >> 2, kq = (s & 3) * 4;
            float4 v = *(const float4*)(W + (size_t)(n0 + n) * K + k0 + kq);
            uint4 u = make_uint4(f2tf32(v.x), f2tf32(v.y), f2tf32(v.z), f2tf32(v.w));
            *(uint4*)&Ws[n][kq] = u;
        }
        __syncthreads();
#pragma unroll
        for (int ks = 0; ks < 2; ks++) {
            int kb = ks * 8;
            uint32_t a0 = As[mt * 16 + gid][kb + tig];
            uint32_t a1 = As[mt * 16 + gid + 8][kb + tig];
            uint32_t a2 = As[mt * 16 + gid][kb + tig + 4];
            uint32_t a3 = As[mt * 16 + gid + 8][kb + tig + 4];
#pragma unroll
            for (int nf = 0; nf < 8; nf++) {
                uint32_t b0 = Ws[nh * 64 + nf * 8 + gid][kb + tig];
                uint32_t b1 = Ws[nh * 64 + nf * 8 + gid][kb + tig + 4];
                asm volatile(
                    "mma.sync.aligned.m16n8k8.row.col.f32.tf32.tf32.f32 "
                    "{%0,%1,%2,%3}, {%4,%5,%6,%7}, {%8,%9}, {%0,%1,%2,%3};"
                    : "+f"(c[nf][0]), "+f"(c[nf][1]), "+f"(c[nf][2]), "+f"(c[nf][3])
                    : "r"(a0), "r"(a1), "r"(a2), "r"(a3), "r"(b0), "r"(b1));
            }
        }
        __syncthreads();
    }

    float* outp = part + (size_t)(kc * gridDim.y + bz) * 64 * N;
    int m0 = mt * 16 + gid;
    int nb = n0 + nh * 64 + tig * 2;
#pragma unroll
    for (int nf = 0; nf < 8; nf++) {
        int n = nb + nf * 8;
        *(float2*)(outp + (size_t)m0 * N + n)       = make_float2(c[nf][0], c[nf][1]);
        *(float2*)(outp + (size_t)(m0 + 8) * N + n) = make_float2(c[nf][2], c[nf][3]);
    }
}

__global__ void reduce_bias(const float* __restrict__ part, RedB rb,
                            int N, int KS, int nBatch) {
    int bz = blockIdx.y;
    int idx = blockIdx.x * 256 + threadIdx.x;
    float s = 0.f;
    size_t per = (size_t)64 * N;
    for (int ks = 0; ks < KS; ks++)
        s += part[(size_t)(ks * nBatch + bz) * per + idx];
    int n = idx & (N - 1);
    if (rb.b1[bz]) s += rb.b1[bz][n];
    if (rb.b2[bz]) s += rb.b2[bz][n];
    rb.O[bz][idx] = s;
}

// --------------- fused split-K reduce + bias + LN(+gelu)(+add) --------------
// grid.x = 128 rows (bz = row>>6, m = row&63); nBatch fixed at 2.
__global__ void __launch_bounds__(256) reduce_ln(
    const float* __restrict__ part, const float* __restrict__ bias, int bstride,
    const float* __restrict__ addrow,
    const float* __restrict__ gamma, const float* __restrict__ beta,
    float* __restrict__ out, int N, int KS, int dogelu, int perhalf) {
    int row = blockIdx.x;
    int bz = row >> 6, m = row & 63;
    int tid = threadIdx.x;
    int nch = N >> 8;                      // N/256 <= 8
    const float* prow = part + ((size_t)bz * 64 + m) * N;
    size_t stride = (size_t)2 * 64 * N;
    float v[8];
    float s = 0.f;
    for (int c = 0; c < nch; c++) {
        int i = c * 256 + tid;
        float acc = bias[bz * bstride + i];
        for (int ks = 0; ks < KS; ks++) acc += prow[(size_t)ks * stride + i];
        if (addrow) acc += addrow[(size_t)row * N + i];
        v[c] = acc; s += acc;
    }
    __shared__ float red[256];
    red[tid] = s; __syncthreads();
    for (int o = 128; o > 0; o >>= 1) { if (tid < o) red[tid] += red[tid + o]; __syncthreads(); }
    float mean = red[0] / N;
    __syncthreads();
    float v2 = 0.f;
    for (int c = 0; c < nch; c++) { float d = v[c] - mean; v2 += d * d; }
    red[tid] = v2; __syncthreads();
    for (int o = 128; o > 0; o >>= 1) { if (tid < o) red[tid] += red[tid + o]; __syncthreads(); }
    float inv = rsqrtf(red[0] / N + 1e-5f);
    int goff = perhalf ? bz * N : 0;
    for (int c = 0; c < nch; c++) {
        int i = c * 256 + tid;
        float o2 = (v[c] - mean) * inv * gamma[goff + i] + beta[goff + i];
        if (dogelu) o2 = 0.5f * o2 * (1.0f + erff(o2 * 0.70710678118654752f));
        out[(size_t)row * N + i] = o2;
    }
}

// ------------- fused split-K reduce + bias + sigmoid gate combine -----------
// BI[i][t][c] = sig(GG[c]) * Y1[i][t][c] + sig(GG[1024+c]) * Y1[i+2][63-t][c]
__global__ void reduce_combine(const float* __restrict__ part,
                               const float* __restrict__ gate_b2, int KS) {
    int idx = blockIdx.x * 256 + threadIdx.x;   // < 2*64*1024
    int i = idx >> 16;
    int t = (idx >> 10) & 63;
    int c = idx & 1023;
    const float* prow = part + ((size_t)i * 64 + t) * 2048;
    size_t stride = (size_t)2 * 64 * 2048;
    float fs = gate_b2[i * 2048 + c];
    float bs = gate_b2[i * 2048 + 1024 + c];
    for (int ks = 0; ks < KS; ks++) {
        fs += prow[(size_t)ks * stride + c];
        bs += prow[(size_t)ks * stride + 1024 + c];
    }
    const float* Y1 = g_scratch + 1572864;  // OFF_Y1
    float f = Y1[(size_t)(i * 64 + t) * 1024 + c];
    float b = Y1[(size_t)((i + 2) * 64 + (63 - t)) * 1024 + c];
    g_scratch[OFF_BI + idx] = sigf(fs) * f + sigf(bs) * b;
}

// ------------------------ persistent LSTM layer (R5) -------------------------
__global__ void __launch_bounds__(256, 1) lstm_persistent(
    const float* __restrict__ Whh, int layer) {
    extern __shared__ float smem[];
    float* sw  = smem;                 // [64][516] weight rows
    float* xzs = smem + 64 * 516;      // [2][64][64]

    float* XZ = g_scratch + OFF_XZ;
    float* Hb = g_scratch + OFF_HB;
    float* Y  = g_scratch + (layer == 0 ? OFF_Y0 : 1572864 /*OFF_Y1*/);

    int blk = blockIdx.x;
    int g = blk >> 5;                  // lstm*2+dir
    int chunk = blk & 31;
    int lstm = g >> 1, dir = g & 1;
    int scanA = lstm * 4 + dir;
    int scanB = lstm * 4 + 2 + dir;
    int u0 = chunk * 16;
    const float* Wg = Whh + (size_t)((lstm * 2 + layer) * 2 + dir) * (2048 * 512);
    int tid = threadIdx.x;
    unsigned* cnt = &g_grp_cnt[g * 32];
    unsigned base = (unsigned)layer * 2048u;

    for (int i4 = tid; i4 < 8192; i4 += 256) {
        int r = i4 >> 7, c4 = i4 & 127;
        int grow = (r >> 4) * 512 + u0 + (r & 15);
        float4 v = *(const float4*)(Wg + (size_t)grow * 512 + c4 * 4);
        *(float4*)(sw + r * 516 + c4 * 4) = v;
    }
    for (int i = tid; i < 8192; i += 256) {
        int sB = i >> 12, t = (i >> 6) & 63, r = i & 63;
        int scan = sB ? scanB : scanA;
        int row = (r >> 4) * 512 + u0 + (r & 15);
        xzs[i] = XZ[(size_t)(scan * 64 + t) * 2048 + row];
    }
    if (tid < 32) {
        int sB = tid >> 4, uu = tid & 15;
        int scan = sB ? scanB : scanA;
        Hb[scan * 512 + u0 + uu] = 0.f;
    }
    __syncthreads();
    if (tid == 0) {
        bar_red_release(cnt);
        unsigned tgt = base + 32u;
        while (ld_acquire(cnt) < tgt) {}
    }
    __syncthreads();

    __shared__ __align__(16) float hA[512], hB[512];
    __shared__ float part[2][4][64];

    // preload h for step 0
    {
        int q = tid & 127;
        const float* src = Hb + (tid < 128 ? scanA : scanB) * 512;
        float4 v = __ldcg((const float4*)src + q);
        float* dst = (tid < 128) ? hA : hB;
        *(float4*)(dst + q * 4) = v;
    }
    __syncthreads();

    float cstate = 0.f;
    int mySB = tid >> 4, myU = tid & 15;
    int myScan = mySB ? scanB : scanA;

    for (int j = 0; j < 64; j++) {
        int t = dir ? (63 - j) : j;
        {
            int r = tid & 63, pp = tid >> 6;
            const float4* wr = (const float4*)(sw + r * 516 + pp * 128);
            const float4* a4 = (const float4*)(hA + pp * 128);
            const float4* b4 = (const float4*)(hB + pp * 128);
            float accA = 0.f, accB = 0.f;
#pragma unroll 8
            for (int i = 0; i < 32; i++) {
                float4 w = wr[i], a = a4[i], b = b4[i];
                accA += w.x * a.x + w.y * a.y + w.z * a.z + w.w * a.w;
                accB += w.x * b.x + w.y * b.y + w.z * b.z + w.w * b.w;
            }
            part[0][pp][r] = accA;
            part[1][pp][r] = accB;
        }
        __syncthreads();
        float* Hnext = Hb + ((j + 1) & 1) * 4096;
        if (tid < 32) {
            float z[4];
#pragma unroll
            for (int gg = 0; gg < 4; gg++) {
                int rr = gg * 16 + myU;
                z[gg] = xzs[mySB * 4096 + t * 64 + rr]
                      + part[mySB][0][rr] + part[mySB][1][rr]
                      + part[mySB][2][rr] + part[mySB][3][rr];
            }
            float c = sigf(z[1]) * cstate + sigf(z[0]) * tanhf(z[2]);
            float h = sigf(z[3]) * tanhf(c);
            cstate = c;
            Hnext[myScan * 512 + u0 + myU] = h;
            int seq = lstm * 2 + mySB;
            Y[(size_t)(seq * 64 + t) * 1024 + dir * 512 + u0 + myU] = h;
        }
        if (j == 63) break;
        if (tid < 32) __syncwarp(0xffffffffu);
        if (tid == 0) {
            bar_red_release(cnt);
            unsigned tgt = base + (unsigned)(j + 2) * 32u;
            while (ld_acquire(cnt) < tgt) {}
        }
        __syncthreads();
        {
            const float* Hp = Hb + ((j + 1) & 1) * 4096;
            int q = tid & 127;
            const float* src = Hp + (tid < 128 ? scanA : scanB) * 512;
            float4 v = __ldcg((const float4*)src + q);
            float* dst = (tid < 128) ? hA : hB;
            *(float4*)(dst + q * 4) = v;
        }
        __syncthreads();
    }
}

// ----------------------------- attention core -------------------------------
__global__ void __launch_bounds__(256) attn_core_kernel() {
    const int h = blockIdx.x;
    const int a = blockIdx.y;
    const float* Q = g_scratch + OFF_Q + (size_t)a * 64 * 1024;
    const float* K = g_scratch + OFF_K + (size_t)a * 64 * 1024;
    const float* V = g_scratch + OFF_V + (size_t)a * 64 * 1024;
    float* AO = g_scratch + OFF_AO + (size_t)a * 64 * 1024;
    __shared__ float KV[64][128];
    __shared__ float Ssm[64][64];
    int tid = threadIdx.x;

    for (int i = tid; i < 64 * 128; i += 256) {
        int m = i >> 7, d = i & 127;
        KV[m][d] = K[m * 1024 + h * 128 + d];
    }
    __syncthreads();
    {
        int n = tid >> 2, p = tid & 3;
        float acc[16];
#pragma unroll
        for (int i = 0; i < 16; i++) acc[i] = 0.f;
        const float* q = Q + n * 1024 + h * 128;
        for (int d = 0; d < 128; d++) {
            float qv = q[d];
#pragma unroll
            for (int i = 0; i < 16; i++) acc[i] += qv * KV[p * 16 + i][d];
        }
        const float scale = 0.08838834764831845f;
#pragma unroll
        for (int i = 0; i < 16; i++) Ssm[n][p * 16 + i] = acc[i] * scale;
    }
    __syncthreads();
    for (int i = tid; i < 64 * 128; i += 256) {
        int m = i >> 7, d = i & 127;
        KV[m][d] = V[m * 1024 + h * 128 + d];
    }
    if (tid < 64) {
        float mx = -1e30f;
        for (int m = 0; m < 64; m++) mx = fmaxf(mx, Ssm[tid][m]);
        float sum = 0.f;
        for (int m = 0; m < 64; m++) { float e = expf(Ssm[tid][m] - mx); Ssm[tid][m] = e; sum += e; }
        float invs = 1.f / sum;
        for (int m = 0; m < 64; m++) Ssm[tid][m] *= invs;
    }
    __syncthreads();
    {
        int n = tid >> 2, p = tid & 3;
        float acc[32];
#pragma unroll
        for (int i = 0; i < 32; i++) acc[i] = 0.f;
        for (int m = 0; m < 64; m++) {
            float w = Ssm[n][m];
#pragma unroll
            for (int i = 0; i < 32; i++) acc[i] += w * KV[m][p * 32 + i];
        }
        for (int i = 0; i < 32; i++)
            AO[n * 1024 + h * 128 + p * 32 + i] = acc[i];
    }
}

// ------------------------------ broadcast -----------------------------------
__global__ void broadcast_kernel(float* __restrict__ out, int total, int half_elems) {
    int j = blockIdx.x * 256 + threadIdx.x;
    if (j >= total) return;
    int half = j / half_elems;
    int rem = j - half * half_elems;
    int i = rem & 65535;
    out[j] = g_scratch[OFF_RES + half * 65536 + i];
}

// ------------------------------- launcher -----------------------------------
extern "C" void kernel_launch(void* const* d_in, const int* in_sizes, int n_in,
                              void* d_out, int out_size) {
    const float* prefix  = (const float*)d_in[0];
    const float* suffix  = (const float*)d_in[1];
    const float* Wih     = (const float*)d_in[2];
    const float* Whh     = (const float*)d_in[3];
    const float* bih     = (const float*)d_in[4];
    const float* bhh     = (const float*)d_in[5];
    const float* attn_w  = (const float*)d_in[6];
    const float* attn_b  = (const float*)d_in[7];
    const float* gate_w1 = (const float*)d_in[8];
    const float* gate_b1 = (const float*)d_in[9];
    const float* gate_lg = (const float*)d_in[10];
    const float* gate_lb = (const float*)d_in[11];
    const float* gate_w2 = (const float*)d_in[12];
    const float* gate_b2 = (const float*)d_in[13];
    const float* out_w1  = (const float*)d_in[14];
    const float* out_b1  = (const float*)d_in[15];
    const float* out_g1  = (const float*)d_in[16];
    const float* out_be1 = (const float*)d_in[17];
    const float* out_w2  = (const float*)d_in[18];
    const float* out_b2  = (const float*)d_in[19];
    const float* out_g2  = (const float*)d_in[20];
    const float* out_be2 = (const float*)d_in[21];
    const float* ln_g    = (const float*)d_in[22];
    const float* ln_b    = (const float*)d_in[23];
    float* out = (float*)d_out;

    float* S = nullptr;
    cudaGetSymbolAddress((void**)&S, g_scratch);
    float* X    = S + OFF_X;
    float* XZ   = S + OFF_XZ;
    float* Y0   = S + OFF_Y0;
    float* Y1   = S + 1572864;
    float* GH2  = S + OFF_GH2;
    float* BI   = S + OFF_BI;
    float* Qp   = S + OFF_Q;
    float* Kp   = S + OFF_K;
    float* Vp   = S + OFF_V;
    float* AO   = S + OFF_AO;
    float* LNO  = S + OFF_LNO;
    float* T2   = S + OFF_T2;
    float* PART = S + OFF_PART;

    const int LSTM_SMEM = (64 * 516 + 8192) * 4;
    static int smem_set = 0;
    if (!smem_set) {
        cudaFuncSetAttribute(lstm_persistent,
                             cudaFuncAttributeMaxDynamicSharedMemorySize, LSTM_SMEM);
        smem_set = 1;
    }

    // 1) embed + PE (zeroes barrier counters)
    embed_kernel<<<1024, 256>>>(prefix, suffix);

    // 2) bilstm
    for (int layer = 0; layer < 2; layer++) {
        const float* src = (layer == 0) ? X : Y0;
        GemmSK gs; RedB rb;
        for (int s = 0; s < 8; s++) {
            int seq = s >> 1, dir = s & 1, lstm = seq >> 1;
            int wi = (lstm * 2 + layer) * 2 + dir;
            gs.A[s]  = src + (size_t)seq * 64 * 1024;
            gs.A2[s] = nullptr;
            gs.W[s]  = Wih + (size_t)wi * 2048 * 1024;
            rb.b1[s] = bih + (size_t)wi * 2048;
            rb.b2[s] = bhh + (size_t)wi * 2048;
            rb.O[s]  = XZ + (size_t)s * 64 * 2048;
        }
        gemm_tc<<<dim3(16, 8, 2), 256>>>(gs, PART, 2048, 1024, 512, 0);
        reduce_bias<<<dim3(512, 8), 256>>>(PART, rb, 2048, 2, 8);
        lstm_persistent<<<128, 256, LSTM_SMEM>>>(Whh, layer);
    }

    // 3) gates: GEMM1 gathers concat(Y1[i], flip(Y1[i+2])) directly
    {
        GemmSK gs;
        for (int i = 0; i < 2; i++) {
            gs.A[i]  = Y1 + (size_t)i * 64 * 1024;
            gs.A2[i] = Y1 + (size_t)(i + 2) * 64 * 1024;
            gs.W[i]  = gate_w1 + (size_t)i * 1024 * 2048;
        }
        gemm_tc<<<dim3(8, 2, 16), 256>>>(gs, PART, 1024, 2048, 128, 1);
        reduce_ln<<<128, 256>>>(PART, gate_b1, 1024, nullptr,
                                gate_lg, gate_lb, GH2, 1024, 16, 1, 1);
    }
    {
        GemmSK gs;
        for (int i = 0; i < 2; i++) {
            gs.A[i]  = GH2 + (size_t)i * 64 * 1024;
            gs.A2[i] = nullptr;
            gs.W[i]  = gate_w2 + (size_t)i * 2048 * 1024;
        }
        gemm_tc<<<dim3(16, 2, 8), 256>>>(gs, PART, 2048, 1024, 128, 0);
        reduce_combine<<<512, 256>>>(PART, gate_b2, 8);
    }

    // 4) cross attention
    {
        GemmSK gs; RedB rb;
        for (int a = 0; a < 2; a++)
            for (int k3 = 0; k3 < 3; k3++) {
                int e = a * 3 + k3;
                int srcIdx = (k3 == 0) ? a : (1 - a);
                gs.A[e]  = BI + (size_t)srcIdx * 64 * 1024;
                gs.A2[e] = nullptr;
                gs.W[e]  = attn_w + (size_t)(a * 4 + k3) * 1024 * 1024;
                rb.b1[e] = attn_b + (size_t)(a * 4 + k3) * 1024;
                rb.b2[e] = nullptr;
                float* dst = (k3 == 0) ? Qp : (k3 == 1) ? Kp : Vp;
                rb.O[e]  = dst + (size_t)a * 64 * 1024;
            }
        gemm_tc<<<dim3(8, 6, 4), 256>>>(gs, PART, 1024, 1024, 256, 0);
        reduce_bias<<<dim3(256, 6), 256>>>(PART, rb, 1024, 4, 6);
    }
    attn_core_kernel<<<dim3(8, 2), 256>>>();
    {
        GemmSK gs;
        for (int a = 0; a < 2; a++) {
            gs.A[a]  = AO + (size_t)a * 64 * 1024;
            gs.A2[a] = nullptr;
            gs.W[a]  = attn_w + (size_t)(a * 4 + 3) * 1024 * 1024;
        }
        gemm_tc<<<dim3(8, 2, 16), 256>>>(gs, PART, 1024, 1024, 64, 0);
        // LNO = LN(BI + PA); bias = attn_b[a][3], stride 4096 between halves
        reduce_ln<<<128, 256>>>(PART, attn_b + 3 * 1024, 4096, BI,
                                ln_g, ln_b, LNO, 1024, 16, 0, 0);
    }

    // 5) output transforms
    {
        GemmSK gs;
        for (int i = 0; i < 2; i++) {
            gs.A[i]  = LNO + (size_t)i * 64 * 1024;
            gs.A2[i] = nullptr;
            gs.W[i]  = out_w1 + (size_t)i * 2048 * 1024;
        }
        gemm_tc<<<dim3(16, 2, 8), 256>>>(gs, PART, 2048, 1024, 128, 0);
        reduce_ln<<<128, 256>>>(PART, out_b1, 2048, nullptr,
                                out_g1, out_be1, T2, 2048, 8, 1, 1);
    }
    {
        GemmSK gs;
        for (int i = 0; i < 2; i++) {
            gs.A[i]  = T2 + (size_t)i * 64 * 2048;
            gs.A2[i] = nullptr;
            gs.W[i]  = out_w2 + (size_t)i * 1024 * 2048;
        }
        gemm_tc<<<dim3(8, 2, 16), 256>>>(gs, PART, 1024, 2048, 128, 0);
        reduce_ln<<<128, 256>>>(PART, out_b2, 1024, nullptr,
                                out_g2, out_be2, S + OFF_RES, 1024, 16, 0, 1);
    }

    // 6) broadcast to all batch rows
    int half_elems = out_size / 2;
    int blocks = (out_size + 255) / 256;
    broadcast_kernel<<<blocks, 256>>>(out, out_size, half_elems);
}

// round 8
// speedup vs baseline: 1.2251x; 1.0377x over previous
#include <cuda_runtime.h>
#include <math.h>
#include <stdint.h>

// ---------------------------------------------------------------------------
// BidirectionalAttentionalPromptEncoder — batch-invariant (B=1) formulation.
// R8: gemm_tc gets a 4-stage cp.async pipeline (raw fp32 tiles, cvt->tf32 at
// fragment load; same rounding + accumulation order as R7). LSTM = R5/R7.
// ---------------------------------------------------------------------------

// ----------------------------- scratch --------------------------------------
#define OFF_X    0          // [4][64][1024]
#define OFF_XZ   262144     // [8][64][2048]
#define OFF_Y0   1310720    // [4][64][1024]
#define OFF_Y1   1572864    // [4][64][1024]
#define OFF_HB   1835008    // [2][8][512]
#define OFF_GH2  2240512    // [2][64][1024]
#define OFF_BI   2633728    // [2][64][1024]
#define OFF_Q    2764800
#define OFF_K    2895872
#define OFF_V    3026944
#define OFF_AO   3158016
#define OFF_LNO  3420160
#define OFF_T2   3813376    // [2][64][2048]
#define OFF_RES  4206592    // [2][64][1024]
#define OFF_PART 4337664    // split-K partials
#define SCRATCH_TOTAL 6434816

__device__ float g_scratch[SCRATCH_TOTAL];

// per-group barrier counters; monotonic within a launch, zeroed by embed_kernel.
__device__ unsigned g_grp_cnt[4 * 32];

__device__ __forceinline__ float sigf(float x) { return 1.0f / (1.0f + expf(-x)); }

__device__ __forceinline__ void bar_red_release(unsigned* cnt) {
    asm volatile("red.release.gpu.global.add.u32 [%0], %1;"
                 :: "l"(cnt), "r"(1u) : "memory");
}
__device__ __forceinline__ unsigned ld_acquire(unsigned* p) {
    unsigned v;
    asm volatile("ld.acquire.gpu.global.u32 %0, [%1];"
                 : "=r"(v) : "l"(p) : "memory");
    return v;
}
__device__ __forceinline__ uint32_t f2tf32(float x) {
    uint32_t r; asm("cvt.rna.tf32.f32 %0, %1;" : "=r"(r) : "f"(x)); return r;
}
__device__ __forceinline__ void cpasync16(void* dst, const void* src) {
    uint32_t d = (uint32_t)__cvta_generic_to_shared(dst);
    asm volatile("cp.async.ca.shared.global [%0], [%1], 16;" :: "r"(d), "l"(src));
}

// ----------------------------- embedding ------------------------------------
__global__ void embed_kernel(const float* __restrict__ pre,
                             const float* __restrict__ suf) {
    if (blockIdx.x == 0 && threadIdx.x < 128) g_grp_cnt[threadIdx.x] = 0;
    int idx = blockIdx.x * 256 + threadIdx.x;   // < 4*64*1024
    int b = idx >> 16;
    int t = (idx >> 10) & 63;
    int c = idx & 1023;
    int st = (b >= 2) ? (63 - t) : t;
    const float* e = (b & 1) ? suf : pre;
    int i2 = c & ~1;
    double div = exp(-log(10000.0) * (double)i2 / 1024.0);
    double ang = (double)st * div;
    float pe = (c & 1) ? (float)cos(ang) : (float)sin(ang);
    g_scratch[OFF_X + idx] = e[st * 1024 + c] + pe;
}

// --------------------------- tf32 tensor GEMM (pipelined) -------------------
// partial[kc][bz] = A[64,K] · W[N,K]^T over K-chunk kc. Block tile 64x128.
// 4-stage cp.async pipeline; fp32 tiles in smem; cvt.rna.tf32 at fragment load.
// gather mode: logical A[m,k] = (k<1024) ? A[m*1024+k] : A2[(63-m)*1024+k-1024].
struct GemmSK {
    const float* A[8];
    const float* A2[8];
    const float* W[8];
};
struct RedB {
    const float* b1[8];
    const float* b2[8];
    float*       O[8];
};

#define GSTAGES 4
#define GSM_A  (64 * 20)           // floats per A stage
#define GSM_W  (128 * 20)          // floats per W stage
#define GSM_TOTAL ((GSTAGES * (GSM_A + GSM_W)) * 4)   // bytes = 61440

__global__ void __launch_bounds__(256, 2) gemm_tc(GemmSK p, float* part,
                                                  int N, int K, int chunkK,
                                                  int gather) {
    extern __shared__ float gsm[];
    float* As = gsm;                       // [GSTAGES][64][20]
    float* Ws = gsm + GSTAGES * GSM_A;     // [GSTAGES][128][20]
    int bz = blockIdx.y, kc = blockIdx.z;
    const float* A  = p.A[bz];
    const float* A2 = p.A2[bz];
    const float* W  = p.W[bz];
    int n0 = blockIdx.x * 128;
    int tid = threadIdx.x;
    int warp = tid >> 5, lane = tid & 31;
    int mt = warp & 3, nh = warp >> 2;
    int gid = lane >> 2, tig = lane & 3;

    // per-thread load coordinates
    int am = tid >> 2, akq = (tid & 3) * 4;            // A: 64x16, 1 x 16B/thread
    int wn0 = (tid * 2) >> 2, wkq0 = ((tid * 2) & 3) * 4;
    int wn1 = (tid * 2 + 1) >> 2, wkq1 = ((tid * 2 + 1) & 3) * 4;

    float c[8][4];
#pragma unroll
    for (int i = 0; i < 8; i++)
#pragma unroll
        for (int j = 0; j < 4; j++) c[i][j] = 0.0f;

    int kbeg = kc * chunkK;
    int niter = chunkK >> 4;

#define G_LOAD(K0, S)                                                          \
    do {                                                                       \
        int k0_ = (K0);                                                        \
        const float* asrc_;                                                    \
        if (gather) {                                                          \
            if (k0_ < 1024) asrc_ = A  + (size_t)am * 1024 + k0_ + akq;        \
            else            asrc_ = A2 + (size_t)(63 - am) * 1024 + (k0_ - 1024) + akq; \
        } else {                                                               \
            asrc_ = A + (size_t)am * K + k0_ + akq;                            \
        }                                                                      \
        cpasync16(As + ((S) * 64 + am) * 20 + akq, asrc_);                     \
        cpasync16(Ws + ((S) * 128 + wn0) * 20 + wkq0,                          \
                  W + (size_t)(n0 + wn0) * K + k0_ + wkq0);                    \
        cpasync16(Ws + ((S) * 128 + wn1) * 20 + wkq1,                          \
                  W + (size_t)(n0 + wn1) * K + k0_ + wkq1);                    \
    } while (0)

    // prologue: 3 stages in flight
#pragma unroll
    for (int s = 0; s < GSTAGES - 1; s++) {
        if (s < niter) G_LOAD(kbeg + s * 16, s);
        asm volatile("cp.async.commit_group;");
    }

    for (int i = 0; i < niter; i++) {
        asm volatile("cp.async.wait_group 2;");
        __syncthreads();
        int nx = i + GSTAGES - 1;
        if (nx < niter) G_LOAD(kbeg + nx * 16, nx & (GSTAGES - 1));
        asm volatile("cp.async.commit_group;");

        int buf = i & (GSTAGES - 1);
        const float* Ab = As + buf * GSM_A;
        const float* Wb = Ws + buf * GSM_W;
#pragma unroll
        for (int ks = 0; ks < 2; ks++) {
            int kb = ks * 8;
            uint32_t a0 = f2tf32(Ab[(mt * 16 + gid) * 20 + kb + tig]);
            uint32_t a1 = f2tf32(Ab[(mt * 16 + gid + 8) * 20 + kb + tig]);
            uint32_t a2 = f2tf32(Ab[(mt * 16 + gid) * 20 + kb + tig + 4]);
            uint32_t a3 = f2tf32(Ab[(mt * 16 + gid + 8) * 20 + kb + tig + 4]);
#pragma unroll
            for (int nf = 0; nf < 8; nf++) {
                uint32_t b0 = f2tf32(Wb[(nh * 64 + nf * 8 + gid) * 20 + kb + tig]);
                uint32_t b1 = f2tf32(Wb[(nh * 64 + nf * 8 + gid) * 20 + kb + tig + 4]);
                asm volatile(
                    "mma.sync.aligned.m16n8k8.row.col.f32.tf32.tf32.f32 "
                    "{%0,%1,%2,%3}, {%4,%5,%6,%7}, {%8,%9}, {%0,%1,%2,%3};"
                    : "+f"(c[nf][0]), "+f"(c[nf][1]), "+f"(c[nf][2]), "+f"(c[nf][3])
                    : "r"(a0), "r"(a1), "r"(a2), "r"(a3), "r"(b0), "r"(b1));
            }
        }
    }
#undef G_LOAD

    float* outp = part + (size_t)(kc * gridDim.y + bz) * 64 * N;
    int m0 = mt * 16 + gid;
    int nb = n0 + nh * 64 + tig * 2;
#pragma unroll
    for (int nf = 0; nf < 8; nf++) {
        int n = nb + nf * 8;
        *(float2*)(outp + (size_t)m0 * N + n)       = make_float2(c[nf][0], c[nf][1]);
        *(float2*)(outp + (size_t)(m0 + 8) * N + n) = make_float2(c[nf][2], c[nf][3]);
    }
}

__global__ void reduce_bias(const float* __restrict__ part, RedB rb,
                            int N, int KS, int nBatch) {
    int bz = blockIdx.y;
    int idx = blockIdx.x * 256 + threadIdx.x;
    float s = 0.f;
    size_t per = (size_t)64 * N;
    for (int ks = 0; ks < KS; ks++)
        s += part[(size_t)(ks * nBatch + bz) * per + idx];
    int n = idx & (N - 1);
    if (rb.b1[bz]) s += rb.b1[bz][n];
    if (rb.b2[bz]) s += rb.b2[bz][n];
    rb.O[bz][idx] = s;
}

// --------------- fused split-K reduce + bias + LN(+gelu)(+add) --------------
__global__ void __launch_bounds__(256) reduce_ln(
    const float* __restrict__ part, const float* __restrict__ bias, int bstride,
    const float* __restrict__ addrow,
    const float* __restrict__ gamma, const float* __restrict__ beta,
    float* __restrict__ out, int N, int KS, int dogelu, int perhalf) {
    int row = blockIdx.x;
    int bz = row >> 6, m = row & 63;
    int tid = threadIdx.x;
    int nch = N >> 8;
    const float* prow = part + ((size_t)bz * 64 + m) * N;
    size_t stride = (size_t)2 * 64 * N;
    float v[8];
    float s = 0.f;
    for (int c = 0; c < nch; c++) {
        int i = c * 256 + tid;
        float acc = bias[bz * bstride + i];
        for (int ks = 0; ks < KS; ks++) acc += prow[(size_t)ks * stride + i];
        if (addrow) acc += addrow[(size_t)row * N + i];
        v[c] = acc; s += acc;
    }
    __shared__ float red[256];
    red[tid] = s; __syncthreads();
    for (int o = 128; o > 0; o >>= 1) { if (tid < o) red[tid] += red[tid + o]; __syncthreads(); }
    float mean = red[0] / N;
    __syncthreads();
    float v2 = 0.f;
    for (int c = 0; c < nch; c++) { float d = v[c] - mean; v2 += d * d; }
    red[tid] = v2; __syncthreads();
    for (int o = 128; o > 0; o >>= 1) { if (tid < o) red[tid] += red[tid + o]; __syncthreads(); }
    float inv = rsqrtf(red[0] / N + 1e-5f);
    int goff = perhalf ? bz * N : 0;
    for (int c = 0; c < nch; c++) {
        int i = c * 256 + tid;
        float o2 = (v[c] - mean) * inv * gamma[goff + i] + beta[goff + i];
        if (dogelu) o2 = 0.5f * o2 * (1.0f + erff(o2 * 0.70710678118654752f));
        out[(size_t)row * N + i] = o2;
    }
}

// ------------- fused split-K reduce + bias + sigmoid gate combine -----------
__global__ void reduce_combine(const float* __restrict__ part,
                               const float* __restrict__ gate_b2, int KS) {
    int idx = blockIdx.x * 256 + threadIdx.x;   // < 2*64*1024
    int i = idx >> 16;
    int t = (idx >> 10) & 63;
    int c = idx & 1023;
    const float* prow = part + ((size_t)i * 64 + t) * 2048;
    size_t stride = (size_t)2 * 64 * 2048;
    float fs = gate_b2[i * 2048 + c];
    float bs = gate_b2[i * 2048 + 1024 + c];
    for (int ks = 0; ks < KS; ks++) {
        fs += prow[(size_t)ks * stride + c];
        bs += prow[(size_t)ks * stride + 1024 + c];
    }
    const float* Y1 = g_scratch + OFF_Y1;
    float f = Y1[(size_t)(i * 64 + t) * 1024 + c];
    float b = Y1[(size_t)((i + 2) * 64 + (63 - t)) * 1024 + c];
    g_scratch[OFF_BI + idx] = sigf(fs) * f + sigf(bs) * b;
}

// ------------------------ persistent LSTM layer (R5) -------------------------
__global__ void __launch_bounds__(256, 1) lstm_persistent(
    const float* __restrict__ Whh, int layer) {
    extern __shared__ float smem[];
    float* sw  = smem;                 // [64][516] weight rows
    float* xzs = smem + 64 * 516;      // [2][64][64]

    float* XZ = g_scratch + OFF_XZ;
    float* Hb = g_scratch + OFF_HB;
    float* Y  = g_scratch + (layer == 0 ? OFF_Y0 : OFF_Y1);

    int blk = blockIdx.x;
    int g = blk >> 5;                  // lstm*2+dir
    int chunk = blk & 31;
    int lstm = g >> 1, dir = g & 1;
    int scanA = lstm * 4 + dir;
    int scanB = lstm * 4 + 2 + dir;
    int u0 = chunk * 16;
    const float* Wg = Whh + (size_t)((lstm * 2 + layer) * 2 + dir) * (2048 * 512);
    int tid = threadIdx.x;
    unsigned* cnt = &g_grp_cnt[g * 32];
    unsigned base = (unsigned)layer * 2048u;

    for (int i4 = tid; i4 < 8192; i4 += 256) {
        int r = i4 >> 7, c4 = i4 & 127;
        int grow = (r >> 4) * 512 + u0 + (r & 15);
        float4 v = *(const float4*)(Wg + (size_t)grow * 512 + c4 * 4);
        *(float4*)(sw + r * 516 + c4 * 4) = v;
    }
    for (int i = tid; i < 8192; i += 256) {
        int sB = i >> 12, t = (i >> 6) & 63, r = i & 63;
        int scan = sB ? scanB : scanA;
        int row = (r >> 4) * 512 + u0 + (r & 15);
        xzs[i] = XZ[(size_t)(scan * 64 + t) * 2048 + row];
    }
    if (tid < 32) {
        int sB = tid >> 4, uu = tid & 15;
        int scan = sB ? scanB : scanA;
        Hb[scan * 512 + u0 + uu] = 0.f;
    }
    __syncthreads();
    if (tid == 0) {
        bar_red_release(cnt);
        unsigned tgt = base + 32u;
        while (ld_acquire(cnt) < tgt) {}
    }
    __syncthreads();

    __shared__ __align__(16) float hA[512], hB[512];
    __shared__ float part[2][4][64];

    {
        int q = tid & 127;
        const float* src = Hb + (tid < 128 ? scanA : scanB) * 512;
        float4 v = __ldcg((const float4*)src + q);
        float* dst = (tid < 128) ? hA : hB;
        *(float4*)(dst + q * 4) = v;
    }
    __syncthreads();

    float cstate = 0.f;
    int mySB = tid >> 4, myU = tid & 15;
    int myScan = mySB ? scanB : scanA;

    for (int j = 0; j < 64; j++) {
        int t = dir ? (63 - j) : j;
        {
            int r = tid & 63, pp = tid >> 6;
            const float4* wr = (const float4*)(sw + r * 516 + pp * 128);
            const float4* a4 = (const float4*)(hA + pp * 128);
            const float4* b4 = (const float4*)(hB + pp * 128);
            float accA = 0.f, accB = 0.f;
#pragma unroll 8
            for (int i = 0; i < 32; i++) {
                float4 w = wr[i], a = a4[i], b = b4[i];
                accA += w.x * a.x + w.y * a.y + w.z * a.z + w.w * a.w;
                accB += w.x * b.x + w.y * b.y + w.z * b.z + w.w * b.w;
            }
            part[0][pp][r] = accA;
            part[1][pp][r] = accB;
        }
        __syncthreads();
        float* Hnext = Hb + ((j + 1) & 1) * 4096;
        if (tid < 32) {
            float z[4];
#pragma unroll
            for (int gg = 0; gg < 4; gg++) {
                int rr = gg * 16 + myU;
                z[gg] = xzs[mySB * 4096 + t * 64 + rr]
                      + part[mySB][0][rr] + part[mySB][1][rr]
                      + part[mySB][2][rr] + part[mySB][3][rr];
            }
            float c = sigf(z[1]) * cstate + sigf(z[0]) * tanhf(z[2]);
            float h = sigf(z[3]) * tanhf(c);
            cstate = c;
            Hnext[myScan * 512 + u0 + myU] = h;
            int seq = lstm * 2 + mySB;
            Y[(size_t)(seq * 64 + t) * 1024 + dir * 512 + u0 + myU] = h;
        }
        if (j == 63) break;
        if (tid < 32) __syncwarp(0xffffffffu);
        if (tid == 0) {
            bar_red_release(cnt);
            unsigned tgt = base + (unsigned)(j + 2) * 32u;
            while (ld_acquire(cnt) < tgt) {}
        }
        __syncthreads();
        {
            const float* Hp = Hb + ((j + 1) & 1) * 4096;
            int q = tid & 127;
            const float* src = Hp + (tid < 128 ? scanA : scanB) * 512;
            float4 v = __ldcg((const float4*)src + q);
            float* dst = (tid < 128) ? hA : hB;
            *(float4*)(dst + q * 4) = v;
        }
        __syncthreads();
    }
}

// ----------------------------- attention core -------------------------------
__global__ void __launch_bounds__(256) attn_core_kernel() {
    const int h = blockIdx.x;
    const int a = blockIdx.y;
    const float* Q = g_scratch + OFF_Q + (size_t)a * 64 * 1024;
    const float* K = g_scratch + OFF_K + (size_t)a * 64 * 1024;
    const float* V = g_scratch + OFF_V + (size_t)a * 64 * 1024;
    float* AO = g_scratch + OFF_AO + (size_t)a * 64 * 1024;
    __shared__ float KV[64][128];
    __shared__ float Ssm[64][64];
    int tid = threadIdx.x;

    for (int i = tid; i < 64 * 128; i += 256) {
        int m = i >> 7, d = i & 127;
        KV[m][d] = K[m * 1024 + h * 128 + d];
    }
    __syncthreads();
    {
        int n = tid >> 2, p = tid & 3;
        float acc[16];
#pragma unroll
        for (int i = 0; i < 16; i++) acc[i] = 0.f;
        const float* q = Q + n * 1024 + h * 128;
        for (int d = 0; d < 128; d++) {
            float qv = q[d];
#pragma unroll
            for (int i = 0; i < 16; i++) acc[i] += qv * KV[p * 16 + i][d];
        }
        const float scale = 0.08838834764831845f;
#pragma unroll
        for (int i = 0; i < 16; i++) Ssm[n][p * 16 + i] = acc[i] * scale;
    }
    __syncthreads();
    for (int i = tid; i < 64 * 128; i += 256) {
        int m = i >> 7, d = i & 127;
        KV[m][d] = V[m * 1024 + h * 128 + d];
    }
    if (tid < 64) {
        float mx = -1e30f;
        for (int m = 0; m < 64; m++) mx = fmaxf(mx, Ssm[tid][m]);
        float sum = 0.f;
        for (int m = 0; m < 64; m++) { float e = expf(Ssm[tid][m] - mx); Ssm[tid][m] = e; sum += e; }
        float invs = 1.f / sum;
        for (int m = 0; m < 64; m++) Ssm[tid][m] *= invs;
    }
    __syncthreads();
    {
        int n = tid >> 2, p = tid & 3;
        float acc[32];
#pragma unroll
        for (int i = 0; i < 32; i++) acc[i] = 0.f;
        for (int m = 0; m < 64; m++) {
            float w = Ssm[n][m];
#pragma unroll
            for (int i = 0; i < 32; i++) acc[i] += w * KV[m][p * 32 + i];
        }
        for (int i = 0; i < 32; i++)
            AO[n * 1024 + h * 128 + p * 32 + i] = acc[i];
    }
}

// ------------------------------ broadcast -----------------------------------
__global__ void broadcast_kernel(float* __restrict__ out, int total, int half_elems) {
    int j = blockIdx.x * 256 + threadIdx.x;
    if (j >= total) return;
    int half = j / half_elems;
    int rem = j - half * half_elems;
    int i = rem & 65535;
    out[j] = g_scratch[OFF_RES + half * 65536 + i];
}

// ------------------------------- launcher -----------------------------------
extern "C" void kernel_launch(void* const* d_in, const int* in_sizes, int n_in,
                              void* d_out, int out_size) {
    const float* prefix  = (const float*)d_in[0];
    const float* suffix  = (const float*)d_in[1];
    const float* Wih     = (const float*)d_in[2];
    const float* Whh     = (const float*)d_in[3];
    const float* bih     = (const float*)d_in[4];
    const float* bhh     = (const float*)d_in[5];
    const float* attn_w  = (const float*)d_in[6];
    const float* attn_b  = (const float*)d_in[7];
    const float* gate_w1 = (const float*)d_in[8];
    const float* gate_b1 = (const float*)d_in[9];
    const float* gate_lg = (const float*)d_in[10];
    const float* gate_lb = (const float*)d_in[11];
    const float* gate_w2 = (const float*)d_in[12];
    const float* gate_b2 = (const float*)d_in[13];
    const float* out_w1  = (const float*)d_in[14];
    const float* out_b1  = (const float*)d_in[15];
    const float* out_g1  = (const float*)d_in[16];
    const float* out_be1 = (const float*)d_in[17];
    const float* out_w2  = (const float*)d_in[18];
    const float* out_b2  = (const float*)d_in[19];
    const float* out_g2  = (const float*)d_in[20];
    const float* out_be2 = (const float*)d_in[21];
    const float* ln_g    = (const float*)d_in[22];
    const float* ln_b    = (const float*)d_in[23];
    float* out = (float*)d_out;

    float* S = nullptr;
    cudaGetSymbolAddress((void**)&S, g_scratch);
    float* X    = S + OFF_X;
    float* XZ   = S + OFF_XZ;
    float* Y0   = S + OFF_Y0;
    float* Y1   = S + OFF_Y1;
    float* GH2  = S + OFF_GH2;
    float* BI   = S + OFF_BI;
    float* Qp   = S + OFF_Q;
    float* Kp   = S + OFF_K;
    float* Vp   = S + OFF_V;
    float* AO   = S + OFF_AO;
    float* LNO  = S + OFF_LNO;
    float* T2   = S + OFF_T2;
    float* PART = S + OFF_PART;

    const int LSTM_SMEM = (64 * 516 + 8192) * 4;
    static int smem_set = 0;
    if (!smem_set) {
        cudaFuncSetAttribute(lstm_persistent,
                             cudaFuncAttributeMaxDynamicSharedMemorySize, LSTM_SMEM);
        cudaFuncSetAttribute(gemm_tc,
                             cudaFuncAttributeMaxDynamicSharedMemorySize, GSM_TOTAL);
        smem_set = 1;
    }

    // 1) embed + PE (zeroes barrier counters)
    embed_kernel<<<1024, 256>>>(prefix, suffix);

    // 2) bilstm
    for (int layer = 0; layer < 2; layer++) {
        const float* src = (layer == 0) ? X : Y0;
        GemmSK gs; RedB rb;
        for (int s = 0; s < 8; s++) {
            int seq = s >> 1, dir = s & 1, lstm = seq >> 1;
            int wi = (lstm * 2 + layer) * 2 + dir;
            gs.A[s]  = src + (size_t)seq * 64 * 1024;
            gs.A2[s] = nullptr;
            gs.W[s]  = Wih + (size_t)wi * 2048 * 1024;
            rb.b1[s] = bih + (size_t)wi * 2048;
            rb.b2[s] = bhh + (size_t)wi * 2048;
            rb.O[s]  = XZ + (size_t)s * 64 * 2048;
        }
        gemm_tc<<<dim3(16, 8, 2), 256, GSM_TOTAL>>>(gs, PART, 2048, 1024, 512, 0);
        reduce_bias<<<dim3(512, 8), 256>>>(PART, rb, 2048, 2, 8);
        lstm_persistent<<<128, 256, LSTM_SMEM>>>(Whh, layer);
    }

    // 3) gates: GEMM1 gathers concat(Y1[i], flip(Y1[i+2])) directly
    {
        GemmSK gs;
        for (int i = 0; i < 2; i++) {
            gs.A[i]  = Y1 + (size_t)i * 64 * 1024;
            gs.A2[i] = Y1 + (size_t)(i + 2) * 64 * 1024;
            gs.W[i]  = gate_w1 + (size_t)i * 1024 * 2048;
        }
        gemm_tc<<<dim3(8, 2, 16), 256, GSM_TOTAL>>>(gs, PART, 1024, 2048, 128, 1);
        reduce_ln<<<128, 256>>>(PART, gate_b1, 1024, nullptr,
                                gate_lg, gate_lb, GH2, 1024, 16, 1, 1);
    }
    {
        GemmSK gs;
        for (int i = 0; i < 2; i++) {
            gs.A[i]  = GH2 + (size_t)i * 64 * 1024;
            gs.A2[i] = nullptr;
            gs.W[i]  = gate_w2 + (size_t)i * 2048 * 1024;
        }
        gemm_tc<<<dim3(16, 2, 8), 256, GSM_TOTAL>>>(gs, PART, 2048, 1024, 128, 0);
        reduce_combine<<<512, 256>>>(PART, gate_b2, 8);
    }

    // 4) cross attention
    {
        GemmSK gs; RedB rb;
        for (int a = 0; a < 2; a++)
            for (int k3 = 0; k3 < 3; k3++) {
                int e = a * 3 + k3;
                int srcIdx = (k3 == 0) ? a : (1 - a);
                gs.A[e]  = BI + (size_t)srcIdx * 64 * 1024;
                gs.A2[e] = nullptr;
                gs.W[e]  = attn_w + (size_t)(a * 4 + k3) * 1024 * 1024;
                rb.b1[e] = attn_b + (size_t)(a * 4 + k3) * 1024;
                rb.b2[e] = nullptr;
                float* dst = (k3 == 0) ? Qp : (k3 == 1) ? Kp : Vp;
                rb.O[e]  = dst + (size_t)a * 64 * 1024;
            }
        gemm_tc<<<dim3(8, 6, 4), 256, GSM_TOTAL>>>(gs, PART, 1024, 1024, 256, 0);
        reduce_bias<<<dim3(256, 6), 256>>>(PART, rb, 1024, 4, 6);
    }
    attn_core_kernel<<<dim3(8, 2), 256>>>();
    {
        GemmSK gs;
        for (int a = 0; a < 2; a++) {
            gs.A[a]  = AO + (size_t)a * 64 * 1024;
            gs.A2[a] = nullptr;
            gs.W[a]  = attn_w + (size_t)(a * 4 + 3) * 1024 * 1024;
        }
        gemm_tc<<<dim3(8, 2, 16), 256, GSM_TOTAL>>>(gs, PART, 1024, 1024, 64, 0);
        reduce_ln<<<128, 256>>>(PART, attn_b + 3 * 1024, 4096, BI,
                                ln_g, ln_b, LNO, 1024, 16, 0, 0);
    }

    // 5) output transforms
    {
        GemmSK gs;
        for (int i = 0; i < 2; i++) {
            gs.A[i]  = LNO + (size_t)i * 64 * 1024;
            gs.A2[i] = nullptr;
            gs.W[i]  = out_w1 + (size_t)i * 2048 * 1024;
        }
        gemm_tc<<<dim3(16, 2, 8), 256, GSM_TOTAL>>>(gs, PART, 2048, 1024, 128, 0);
        reduce_ln<<<128, 256>>>(PART, out_b1, 2048, nullptr,
                                out_g1, out_be1, T2, 2048, 8, 1, 1);
    }
    {
        GemmSK gs;
        for (int i = 0; i < 2; i++) {
            gs.A[i]  = T2 + (size_t)i * 64 * 2048;
            gs.A2[i] = nullptr;
            gs.W[i]  = out_w2 + (size_t)i * 1024 * 2048;
        }
        gemm_tc<<<dim3(8, 2, 16), 256, GSM_TOTAL>>>(gs, PART, 1024, 2048, 128, 0);
        reduce_ln<<<128, 256>>>(PART, out_b2, 1024, nullptr,
                                out_g2, out_be2, S + OFF_RES, 1024, 16, 0, 1);
    }

    // 6) broadcast to all batch rows
    int half_elems = out_size / 2;
    int blocks = (out_size + 255) / 256;
    broadcast_kernel<<<blocks, 256>>>(out, out_size, half_elems);
}